// round 2
// baseline (speedup 1.0000x reference)
#include <cuda_runtime.h>

#define NN 50000
#define EE 1600000
#define RR 50
#define BB 30
#define HH 16
#define CC 4
#define NH4 (NN * HH / 4)   // 200000 float4 columns

// ---------------- scratch (device globals; no allocation) ----------------
__device__ float4 g_w1[(size_t)RR * NN * HH / 4];  // [R,N,H] as float4, 160MB
__device__ float4 g_w2[RR * HH * CC / 4];          // [R,H,C] 800 float4
__device__ float4 g_xsum[NN * HH / 4];             // layer1 scatter accumulator
__device__ float4 g_x[NN * HH / 4];                // relu'd hidden features
__device__ float  g_cnt[NN];                       // in-degree (float)
__device__ float4 g_osum[NN];                      // layer2 scatter accumulator [N,C]

// vectorized global reduction (sm_90+)
__device__ __forceinline__ void red4(float4* p, float4 v) {
    asm volatile("red.global.add.v4.f32 [%0], {%1, %2, %3, %4};"
                 :: "l"(p), "f"(v.x), "f"(v.y), "f"(v.z), "f"(v.w)
                 : "memory");
}

__device__ __forceinline__ void fma4(float4& a, float s, float4 w) {
    a.x += s * w.x; a.y += s * w.y; a.z += s * w.z; a.w += s * w.w;
}

// ---------------- K0: zero the accumulators ----------------
__global__ void k_zero() {
    int i = blockIdx.x * blockDim.x + threadIdx.x;
    float4 z = make_float4(0.f, 0.f, 0.f, 0.f);
    if (i < NN * HH / 4) g_xsum[i] = z;
    if (i < NN) { g_cnt[i] = 0.f; g_osum[i] = z; }
}

// ---------------- K_w2: w2[r,h,c] = sum_b comp2[r,b] * basis2[b,h,c] ----------------
__global__ void k_w2(const float* __restrict__ comp2, const float* __restrict__ basis2) {
    __shared__ float sc[RR * BB];        // 1500
    __shared__ float sb[BB * HH * CC];   // 1920
    for (int i = threadIdx.x; i < RR * BB; i += blockDim.x) sc[i] = comp2[i];
    for (int i = threadIdx.x; i < BB * HH * CC; i += blockDim.x) sb[i] = basis2[i];
    __syncthreads();
    float* w2f = (float*)g_w2;
    for (int i = threadIdx.x; i < RR * HH * CC; i += blockDim.x) {
        int r = i / (HH * CC);
        int hc = i % (HH * CC);
        float acc = 0.f;
        #pragma unroll
        for (int b = 0; b < BB; b++) acc += sc[r * BB + b] * sb[b * HH * CC + hc];
        w2f[i] = acc;
    }
}

// ---------------- K1: w1[r,n,h] = sum_b comp1[r,b] * basis1[b,n,h] ----------------
// One thread per float4 column (n,h4). Basis column (30 float4) lives in registers,
// looped over all 50 relations. FFMA-issue bound by design.
__global__ void __launch_bounds__(128) k_w1(const float4* __restrict__ basis1,
                                            const float* __restrict__ comp1) {
    __shared__ float sc[RR * BB];
    for (int i = threadIdx.x; i < RR * BB; i += blockDim.x) sc[i] = comp1[i];
    __syncthreads();

    int i4 = blockIdx.x * blockDim.x + threadIdx.x;
    if (i4 >= NH4) return;

    float4 bv[BB];
    #pragma unroll
    for (int b = 0; b < BB; b++) bv[b] = basis1[(size_t)b * NH4 + i4];

    for (int r = 0; r < RR; r++) {
        float4 acc = make_float4(0.f, 0.f, 0.f, 0.f);
        const float* cr = &sc[r * BB];
        #pragma unroll
        for (int b = 0; b < BB; b++) fma4(acc, cr[b], bv[b]);
        g_w1[(size_t)r * NH4 + i4] = acc;
    }
}

// ---------------- K2: layer-1 edge pass: gather w1[(t,s)], scatter-add to xsum[dst] ----------------
__global__ void k_edge1(const int* __restrict__ ei, const int* __restrict__ et) {
    int e = blockIdx.x * blockDim.x + threadIdx.x;
    if (e >= EE) return;
    int s = ei[e];
    int d = ei[EE + e];
    int t = et[e];
    const float4* row = g_w1 + ((size_t)t * NN + s) * 4;
    float4 v0 = row[0], v1 = row[1], v2 = row[2], v3 = row[3];
    float4* dst = g_xsum + d * 4;
    red4(dst + 0, v0);
    red4(dst + 1, v1);
    red4(dst + 2, v2);
    red4(dst + 3, v3);
    atomicAdd(&g_cnt[d], 1.0f);
}

// ---------------- K3: x = relu(xsum/max(cnt,1) + root1 + bias1) ----------------
__global__ void k_x(const float4* __restrict__ root1, const float4* __restrict__ bias1) {
    int n = blockIdx.x * blockDim.x + threadIdx.x;
    if (n >= NN) return;
    float inv = 1.f / fmaxf(g_cnt[n], 1.f);
    #pragma unroll
    for (int j = 0; j < 4; j++) {
        float4 a = g_xsum[n * 4 + j];
        float4 rv = root1[n * 4 + j];
        float4 bv = bias1[j];
        float4 o;
        o.x = fmaxf(a.x * inv + rv.x + bv.x, 0.f);
        o.y = fmaxf(a.y * inv + rv.y + bv.y, 0.f);
        o.z = fmaxf(a.z * inv + rv.z + bv.z, 0.f);
        o.w = fmaxf(a.w * inv + rv.w + bv.w, 0.f);
        g_x[n * 4 + j] = o;
    }
}

// ---------------- K4: layer-2 edge pass: msg = x[src] @ w2[t], scatter-add ----------------
__global__ void k_edge2(const int* __restrict__ ei, const int* __restrict__ et) {
    __shared__ float4 sw2[RR * HH];  // 800 float4 = 12.8 KB
    for (int i = threadIdx.x; i < RR * HH; i += blockDim.x) sw2[i] = g_w2[i];
    __syncthreads();

    int e = blockIdx.x * blockDim.x + threadIdx.x;
    if (e >= EE) return;
    int s = ei[e];
    int d = ei[EE + e];
    int t = et[e];

    const float4* xr = g_x + s * 4;
    float4 x0 = xr[0], x1 = xr[1], x2 = xr[2], x3 = xr[3];
    const float4* w = &sw2[t * HH];

    float4 acc = make_float4(0.f, 0.f, 0.f, 0.f);
    fma4(acc, x0.x, w[0]);  fma4(acc, x0.y, w[1]);  fma4(acc, x0.z, w[2]);  fma4(acc, x0.w, w[3]);
    fma4(acc, x1.x, w[4]);  fma4(acc, x1.y, w[5]);  fma4(acc, x1.z, w[6]);  fma4(acc, x1.w, w[7]);
    fma4(acc, x2.x, w[8]);  fma4(acc, x2.y, w[9]);  fma4(acc, x2.z, w[10]); fma4(acc, x2.w, w[11]);
    fma4(acc, x3.x, w[12]); fma4(acc, x3.y, w[13]); fma4(acc, x3.z, w[14]); fma4(acc, x3.w, w[15]);

    red4(&g_osum[d], acc);
}

// ---------------- K5: out = log_softmax(osum/max(cnt,1) + x @ root2 + bias2) ----------------
__global__ void k_out(const float4* __restrict__ root2, const float4* __restrict__ bias2,
                      float4* __restrict__ out) {
    __shared__ float4 sr2[HH];  // root2 [H,C] = 16 float4
    __shared__ float4 sb2;
    if (threadIdx.x < HH) sr2[threadIdx.x] = root2[threadIdx.x];
    if (threadIdx.x == 0) sb2 = bias2[0];
    __syncthreads();

    int n = blockIdx.x * blockDim.x + threadIdx.x;
    if (n >= NN) return;

    float inv = 1.f / fmaxf(g_cnt[n], 1.f);
    float4 os = g_osum[n];
    float4 acc;
    acc.x = os.x * inv + sb2.x;
    acc.y = os.y * inv + sb2.y;
    acc.z = os.z * inv + sb2.z;
    acc.w = os.w * inv + sb2.w;

    const float4* xr = g_x + n * 4;
    #pragma unroll
    for (int j = 0; j < 4; j++) {
        float4 xv = xr[j];
        fma4(acc, xv.x, sr2[j * 4 + 0]);
        fma4(acc, xv.y, sr2[j * 4 + 1]);
        fma4(acc, xv.z, sr2[j * 4 + 2]);
        fma4(acc, xv.w, sr2[j * 4 + 3]);
    }

    // log_softmax over C=4
    float m = fmaxf(fmaxf(acc.x, acc.y), fmaxf(acc.z, acc.w));
    float se = expf(acc.x - m) + expf(acc.y - m) + expf(acc.z - m) + expf(acc.w - m);
    float l = m + logf(se);
    float4 o;
    o.x = acc.x - l; o.y = acc.y - l; o.z = acc.z - l; o.w = acc.w - l;
    out[n] = o;
}

// ---------------- launcher ----------------
extern "C" void kernel_launch(void* const* d_in, const int* in_sizes, int n_in,
                              void* d_out, int out_size) {
    const int*    ei        = (const int*)d_in[0];         // edge_index [2,E] int32 (x64 disabled in JAX)
    const int*    et        = (const int*)d_in[1];         // edge_type  [E]   int32
    // d_in[2] edge_norm: unused by the reference forward
    const float*  basis1    = (const float*)d_in[3];       // [B,N,H]
    const float*  comp1     = (const float*)d_in[4];       // [R,B]
    const float4* root1     = (const float4*)d_in[5];      // [N,H]
    const float4* bias1     = (const float4*)d_in[6];      // [H]
    const float*  basis2    = (const float*)d_in[7];       // [B,H,C]
    const float*  comp2     = (const float*)d_in[8];       // [R,B]
    const float4* root2     = (const float4*)d_in[9];      // [H,C]
    const float4* bias2     = (const float4*)d_in[10];     // [C]
    float4* out = (float4*)d_out;

    (void)in_sizes; (void)n_in; (void)out_size;

    k_zero <<<(NH4 + 255) / 256, 256>>>();
    k_w2   <<<1, 256>>>(comp2, basis2);
    k_w1   <<<(NH4 + 127) / 128, 128>>>((const float4*)basis1, comp1);
    k_edge1<<<(EE + 255) / 256, 256>>>(ei, et);
    k_x    <<<(NN + 255) / 256, 256>>>(root1, bias1);
    k_edge2<<<(EE + 255) / 256, 256>>>(ei, et);
    k_out  <<<(NN + 255) / 256, 256>>>(root2, bias2, out);
}

// round 3
// speedup vs baseline: 1.0682x; 1.0682x over previous
#include <cuda_runtime.h>
#include <cuda_fp16.h>

#define NN 50000
#define EE 1600000
#define RR 50
#define BB 30
#define HH 16
#define CC 4
#define NH4 (NN * HH / 4)   // 200000 float4 columns

// ---------------- scratch (device globals; no allocation) ----------------
__device__ uint4  g_w1h[(size_t)RR * NN * 2];      // [R,N,H] fp16, 2 uint4 (32B) per row, 80MB
__device__ float4 g_w2[RR * HH * CC / 4];          // [R,H,C] 800 float4
__device__ float4 g_xsum[NN * HH / 4];             // layer1 scatter accumulator
__device__ float4 g_x[NN * HH / 4];                // relu'd hidden features
__device__ float  g_cnt[NN];                       // in-degree (float)
__device__ float4 g_osum[NN];                      // layer2 scatter accumulator [N,C]

// vectorized global reduction (sm_90+)
__device__ __forceinline__ void red4(float4* p, float4 v) {
    asm volatile("red.global.add.v4.f32 [%0], {%1, %2, %3, %4};"
                 :: "l"(p), "f"(v.x), "f"(v.y), "f"(v.z), "f"(v.w)
                 : "memory");
}

__device__ __forceinline__ void fma4(float4& a, float s, float4 w) {
    a.x += s * w.x; a.y += s * w.y; a.z += s * w.z; a.w += s * w.w;
}

// ---- packed f32x2 helpers (FFMA2: 2x FFMA throughput, PTX-only) ----
__device__ __forceinline__ unsigned long long pack2(float x, float y) {
    unsigned long long r;
    asm("mov.b64 %0, {%1, %2};" : "=l"(r) : "f"(x), "f"(y));
    return r;
}
__device__ __forceinline__ void unpack2(unsigned long long v, float& x, float& y) {
    asm("mov.b64 {%0, %1}, %2;" : "=f"(x), "=f"(y) : "l"(v));
}
__device__ __forceinline__ void fma2(unsigned long long& d,
                                     unsigned long long a, unsigned long long b) {
    asm("fma.rn.f32x2 %0, %1, %2, %0;" : "+l"(d) : "l"(a), "l"(b));
}

// ---------------- K0: zero the accumulators ----------------
__global__ void k_zero() {
    int i = blockIdx.x * blockDim.x + threadIdx.x;
    float4 z = make_float4(0.f, 0.f, 0.f, 0.f);
    if (i < NN * HH / 4) g_xsum[i] = z;
    if (i < NN) { g_cnt[i] = 0.f; g_osum[i] = z; }
}

// ---------------- K_w2: w2[r,h,c] = sum_b comp2[r,b] * basis2[b,h,c] ----------------
__global__ void k_w2(const float* __restrict__ comp2, const float* __restrict__ basis2) {
    __shared__ float sc[RR * BB];
    __shared__ float sb[BB * HH * CC];
    for (int i = threadIdx.x; i < RR * BB; i += blockDim.x) sc[i] = comp2[i];
    for (int i = threadIdx.x; i < BB * HH * CC; i += blockDim.x) sb[i] = basis2[i];
    __syncthreads();
    float* w2f = (float*)g_w2;
    for (int i = threadIdx.x; i < RR * HH * CC; i += blockDim.x) {
        int r = i / (HH * CC);
        int hc = i % (HH * CC);
        float acc = 0.f;
        #pragma unroll
        for (int b = 0; b < BB; b++) acc += sc[r * BB + b] * sb[b * HH * CC + hc];
        w2f[i] = acc;
    }
}

// ---------------- K1: w1[r,n,h] = sum_b comp1[r,b] * basis1[b,n,h], stored fp16 ----------------
// One thread per float4 column (n,h4). Basis column in registers as 2 packed
// f32x2 chains -> fma.rn.f32x2 saturates the FMA pipe at 2 lane-FMAs/instr.
__global__ void __launch_bounds__(128) k_w1(const float4* __restrict__ basis1,
                                            const float* __restrict__ comp1) {
    __shared__ float sc[RR * BB];
    for (int i = threadIdx.x; i < RR * BB; i += blockDim.x) sc[i] = comp1[i];
    __syncthreads();

    int i4 = blockIdx.x * blockDim.x + threadIdx.x;
    if (i4 >= NH4) return;

    unsigned long long blo[BB], bhi[BB];
    #pragma unroll
    for (int b = 0; b < BB; b++) {
        float4 v = basis1[(size_t)b * NH4 + i4];
        blo[b] = pack2(v.x, v.y);
        bhi[b] = pack2(v.z, v.w);
    }

    int n  = i4 >> 2;
    int hq = i4 & 3;
    uint2* outp = (uint2*)g_w1h;

    for (int r = 0; r < RR; r++) {
        unsigned long long a0 = 0ull, a1 = 0ull;   // (0.f, 0.f) bit pattern
        const float* cr = &sc[r * BB];
        #pragma unroll
        for (int b = 0; b < BB; b++) {
            float c = cr[b];
            unsigned long long cc = pack2(c, c);
            fma2(a0, cc, blo[b]);
            fma2(a1, cc, bhi[b]);
        }
        float f0, f1, f2, f3;
        unpack2(a0, f0, f1);
        unpack2(a1, f2, f3);
        __half2 h0 = __floats2half2_rn(f0, f1);
        __half2 h1 = __floats2half2_rn(f2, f3);
        uint2 o;
        o.x = *(unsigned int*)&h0;
        o.y = *(unsigned int*)&h1;
        outp[(((size_t)r * NN + n) << 2) + hq] = o;
    }
}

// ---------------- K2: layer-1 edge pass: gather fp16 w1[(t,s)] (32B), scatter-add fp32 ----------------
__global__ void k_edge1(const int* __restrict__ ei, const int* __restrict__ et) {
    int e = blockIdx.x * blockDim.x + threadIdx.x;
    if (e >= EE) return;
    int s = ei[e];
    int d = ei[EE + e];
    int t = et[e];
    const uint4* row = g_w1h + ((size_t)t * NN + s) * 2;
    uint4 a = row[0], b = row[1];

    float2 f0 = __half22float2(*(__half2*)&a.x);
    float2 f1 = __half22float2(*(__half2*)&a.y);
    float2 f2 = __half22float2(*(__half2*)&a.z);
    float2 f3 = __half22float2(*(__half2*)&a.w);
    float2 f4 = __half22float2(*(__half2*)&b.x);
    float2 f5 = __half22float2(*(__half2*)&b.y);
    float2 f6 = __half22float2(*(__half2*)&b.z);
    float2 f7 = __half22float2(*(__half2*)&b.w);

    float4* dst = g_xsum + d * 4;
    red4(dst + 0, make_float4(f0.x, f0.y, f1.x, f1.y));
    red4(dst + 1, make_float4(f2.x, f2.y, f3.x, f3.y));
    red4(dst + 2, make_float4(f4.x, f4.y, f5.x, f5.y));
    red4(dst + 3, make_float4(f6.x, f6.y, f7.x, f7.y));
    atomicAdd(&g_cnt[d], 1.0f);
}

// ---------------- K3: x = relu(xsum/max(cnt,1) + root1 + bias1) ----------------
__global__ void k_x(const float4* __restrict__ root1, const float4* __restrict__ bias1) {
    int n = blockIdx.x * blockDim.x + threadIdx.x;
    if (n >= NN) return;
    float inv = 1.f / fmaxf(g_cnt[n], 1.f);
    #pragma unroll
    for (int j = 0; j < 4; j++) {
        float4 a = g_xsum[n * 4 + j];
        float4 rv = root1[n * 4 + j];
        float4 bv = bias1[j];
        float4 o;
        o.x = fmaxf(a.x * inv + rv.x + bv.x, 0.f);
        o.y = fmaxf(a.y * inv + rv.y + bv.y, 0.f);
        o.z = fmaxf(a.z * inv + rv.z + bv.z, 0.f);
        o.w = fmaxf(a.w * inv + rv.w + bv.w, 0.f);
        g_x[n * 4 + j] = o;
    }
}

// ---------------- K4: layer-2 edge pass: msg = x[src] @ w2[t], scatter-add ----------------
__global__ void k_edge2(const int* __restrict__ ei, const int* __restrict__ et) {
    __shared__ float4 sw2[RR * HH];  // 12.8 KB
    for (int i = threadIdx.x; i < RR * HH; i += blockDim.x) sw2[i] = g_w2[i];
    __syncthreads();

    int e = blockIdx.x * blockDim.x + threadIdx.x;
    if (e >= EE) return;
    int s = ei[e];
    int d = ei[EE + e];
    int t = et[e];

    const float4* xr = g_x + s * 4;
    float4 x0 = xr[0], x1 = xr[1], x2 = xr[2], x3 = xr[3];
    const float4* w = &sw2[t * HH];

    float4 acc = make_float4(0.f, 0.f, 0.f, 0.f);
    fma4(acc, x0.x, w[0]);  fma4(acc, x0.y, w[1]);  fma4(acc, x0.z, w[2]);  fma4(acc, x0.w, w[3]);
    fma4(acc, x1.x, w[4]);  fma4(acc, x1.y, w[5]);  fma4(acc, x1.z, w[6]);  fma4(acc, x1.w, w[7]);
    fma4(acc, x2.x, w[8]);  fma4(acc, x2.y, w[9]);  fma4(acc, x2.z, w[10]); fma4(acc, x2.w, w[11]);
    fma4(acc, x3.x, w[12]); fma4(acc, x3.y, w[13]); fma4(acc, x3.z, w[14]); fma4(acc, x3.w, w[15]);

    red4(&g_osum[d], acc);
}

// ---------------- K5: out = log_softmax(osum/max(cnt,1) + x @ root2 + bias2) ----------------
__global__ void k_out(const float4* __restrict__ root2, const float4* __restrict__ bias2,
                      float4* __restrict__ out) {
    __shared__ float4 sr2[HH];
    __shared__ float4 sb2;
    if (threadIdx.x < HH) sr2[threadIdx.x] = root2[threadIdx.x];
    if (threadIdx.x == 0) sb2 = bias2[0];
    __syncthreads();

    int n = blockIdx.x * blockDim.x + threadIdx.x;
    if (n >= NN) return;

    float inv = 1.f / fmaxf(g_cnt[n], 1.f);
    float4 os = g_osum[n];
    float4 acc;
    acc.x = os.x * inv + sb2.x;
    acc.y = os.y * inv + sb2.y;
    acc.z = os.z * inv + sb2.z;
    acc.w = os.w * inv + sb2.w;

    const float4* xr = g_x + n * 4;
    #pragma unroll
    for (int j = 0; j < 4; j++) {
        float4 xv = xr[j];
        fma4(acc, xv.x, sr2[j * 4 + 0]);
        fma4(acc, xv.y, sr2[j * 4 + 1]);
        fma4(acc, xv.z, sr2[j * 4 + 2]);
        fma4(acc, xv.w, sr2[j * 4 + 3]);
    }

    float m = fmaxf(fmaxf(acc.x, acc.y), fmaxf(acc.z, acc.w));
    float se = expf(acc.x - m) + expf(acc.y - m) + expf(acc.z - m) + expf(acc.w - m);
    float l = m + logf(se);
    float4 o;
    o.x = acc.x - l; o.y = acc.y - l; o.z = acc.z - l; o.w = acc.w - l;
    out[n] = o;
}

// ---------------- launcher ----------------
extern "C" void kernel_launch(void* const* d_in, const int* in_sizes, int n_in,
                              void* d_out, int out_size) {
    const int*    ei        = (const int*)d_in[0];         // edge_index [2,E] int32
    const int*    et        = (const int*)d_in[1];         // edge_type  [E]   int32
    // d_in[2] edge_norm: unused by the reference forward
    const float*  basis1    = (const float*)d_in[3];       // [B,N,H]
    const float*  comp1     = (const float*)d_in[4];       // [R,B]
    const float4* root1     = (const float4*)d_in[5];      // [N,H]
    const float4* bias1     = (const float4*)d_in[6];      // [H]
    const float*  basis2    = (const float*)d_in[7];       // [B,H,C]
    const float*  comp2     = (const float*)d_in[8];       // [R,B]
    const float4* root2     = (const float4*)d_in[9];      // [H,C]
    const float4* bias2     = (const float4*)d_in[10];     // [C]
    float4* out = (float4*)d_out;

    (void)in_sizes; (void)n_in; (void)out_size;

    k_zero <<<(NH4 + 255) / 256, 256>>>();
    k_w2   <<<1, 256>>>(comp2, basis2);
    k_w1   <<<(NH4 + 127) / 128, 128>>>((const float4*)basis1, comp1);
    k_edge1<<<(EE + 255) / 256, 256>>>(ei, et);
    k_x    <<<(NN + 255) / 256, 256>>>(root1, bias1);
    k_edge2<<<(EE + 255) / 256, 256>>>(ei, et);
    k_out  <<<(NN + 255) / 256, 256>>>(root2, bias2, out);
}

// round 4
// speedup vs baseline: 1.1177x; 1.0463x over previous
#include <cuda_runtime.h>
#include <cuda_fp16.h>

#define NN 50000
#define EE 1600000
#define RR 50
#define BB 30
#define HH 16
#define CC 4
#define NH4 (NN * HH / 4)   // 200000 float4 columns

// ---------------- scratch (device globals; no allocation) ----------------
__device__ uint4  g_w1h[(size_t)RR * NN * 2];      // [R,N,H] fp16: 2x uint4 (32B)/row, 80MB
__device__ float4 g_w2[RR * HH * CC / 4];          // [R,H,C]
__device__ uint4  g_xsumh[NN * 2];                 // layer1 accumulator, fp16 (8 halves per uint4)
__device__ float4 g_x[NN * HH / 4];                // relu'd hidden features (fp32)
__device__ float  g_cnt[NN];                       // in-degree (float)
__device__ float4 g_osum[NN];                      // layer2 accumulator [N,C] fp32

// fp32 v4 reduction (proven on sm_103a)
__device__ __forceinline__ void red4(float4* p, float4 v) {
    asm volatile("red.global.add.v4.f32 [%0], {%1, %2, %3, %4};"
                 :: "l"(p), "f"(v.x), "f"(v.y), "f"(v.z), "f"(v.w)
                 : "memory");
}
// fp16x2 v4 reduction: adds 8 packed halves in one atomic op
__device__ __forceinline__ void red4h(uint4* p, uint4 v) {
    asm volatile("red.global.add.noftz.v4.f16x2 [%0], {%1, %2, %3, %4};"
                 :: "l"(p), "r"(v.x), "r"(v.y), "r"(v.z), "r"(v.w)
                 : "memory");
}

__device__ __forceinline__ void fma4(float4& a, float s, float4 w) {
    a.x += s * w.x; a.y += s * w.y; a.z += s * w.z; a.w += s * w.w;
}

// ---- packed f32x2 helpers ----
__device__ __forceinline__ unsigned long long pack2(float x, float y) {
    unsigned long long r;
    asm("mov.b64 %0, {%1, %2};" : "=l"(r) : "f"(x), "f"(y));
    return r;
}
__device__ __forceinline__ void unpack2(unsigned long long v, float& x, float& y) {
    asm("mov.b64 {%0, %1}, %2;" : "=f"(x), "=f"(y) : "l"(v));
}
__device__ __forceinline__ void fma2(unsigned long long& d,
                                     unsigned long long a, unsigned long long b) {
    asm("fma.rn.f32x2 %0, %1, %2, %0;" : "+l"(d) : "l"(a), "l"(b));
}

// ---------------- K0: zero the accumulators ----------------
__global__ void k_zero() {
    int i = blockIdx.x * blockDim.x + threadIdx.x;
    uint4 zu = make_uint4(0u, 0u, 0u, 0u);
    if (i < NN * 2) g_xsumh[i] = zu;
    if (i < NN) { g_cnt[i] = 0.f; g_osum[i] = make_float4(0.f, 0.f, 0.f, 0.f); }
}

// ---------------- K_w2: w2[r,h,c] = sum_b comp2[r,b] * basis2[b,h,c] ----------------
__global__ void k_w2(const float* __restrict__ comp2, const float* __restrict__ basis2) {
    __shared__ float sc[RR * BB];
    __shared__ float sb[BB * HH * CC];
    for (int i = threadIdx.x; i < RR * BB; i += blockDim.x) sc[i] = comp2[i];
    for (int i = threadIdx.x; i < BB * HH * CC; i += blockDim.x) sb[i] = basis2[i];
    __syncthreads();
    float* w2f = (float*)g_w2;
    for (int i = threadIdx.x; i < RR * HH * CC; i += blockDim.x) {
        int r = i / (HH * CC);
        int hc = i % (HH * CC);
        float acc = 0.f;
        #pragma unroll
        for (int b = 0; b < BB; b++) acc += sc[r * BB + b] * sb[b * HH * CC + hc];
        w2f[i] = acc;
    }
}

// ---------------- K1: w1[r,n,h] = sum_b comp1[r,b] * basis1[b,n,h], stored fp16 ----------------
// Coefficients pre-packed as (c,c) u64 in smem; inner loop = LDS.64 broadcast + 2x fma.rn.f32x2.
__global__ void __launch_bounds__(128, 3) k_w1(const float4* __restrict__ basis1,
                                               const float* __restrict__ comp1) {
    __shared__ unsigned long long scc[RR * BB];   // 12 KB
    for (int i = threadIdx.x; i < RR * BB; i += blockDim.x) {
        float c = comp1[i];
        scc[i] = pack2(c, c);
    }
    __syncthreads();

    int i4 = blockIdx.x * blockDim.x + threadIdx.x;
    if (i4 >= NH4) return;

    unsigned long long blo[BB], bhi[BB];
    #pragma unroll
    for (int b = 0; b < BB; b++) {
        float4 v = basis1[(size_t)b * NH4 + i4];
        blo[b] = pack2(v.x, v.y);
        bhi[b] = pack2(v.z, v.w);
    }

    int n  = i4 >> 2;
    int hq = i4 & 3;
    uint2* outp = (uint2*)g_w1h;

    for (int r = 0; r < RR; r++) {
        unsigned long long a0 = 0ull, a1 = 0ull;
        const unsigned long long* cr = &scc[r * BB];
        #pragma unroll
        for (int b = 0; b < BB; b++) {
            unsigned long long cc = cr[b];
            fma2(a0, cc, blo[b]);
            fma2(a1, cc, bhi[b]);
        }
        float f0, f1, f2, f3;
        unpack2(a0, f0, f1);
        unpack2(a1, f2, f3);
        __half2 h0 = __floats2half2_rn(f0, f1);
        __half2 h1 = __floats2half2_rn(f2, f3);
        uint2 o;
        o.x = *(unsigned int*)&h0;
        o.y = *(unsigned int*)&h1;
        outp[(((size_t)r * NN + n) << 2) + hq] = o;
    }
}

// ---------------- K2: layer-1 edge pass: gather fp16 w1 row (32B), fp16x2 vector RED ----------------
__global__ void k_edge1(const int* __restrict__ ei, const int* __restrict__ et) {
    int e = blockIdx.x * blockDim.x + threadIdx.x;
    if (e >= EE) return;
    int s = ei[e];
    int d = ei[EE + e];
    int t = et[e];
    const uint4* row = g_w1h + ((size_t)t * NN + s) * 2;
    uint4 a = row[0], b = row[1];
    uint4* dst = g_xsumh + d * 2;
    red4h(dst + 0, a);
    red4h(dst + 1, b);
    atomicAdd(&g_cnt[d], 1.0f);
}

// ---------------- K3: x = relu(xsum/max(cnt,1) + root1 + bias1) ----------------
__global__ void k_x(const float4* __restrict__ root1, const float4* __restrict__ bias1) {
    int n = blockIdx.x * blockDim.x + threadIdx.x;
    if (n >= NN) return;
    float inv = 1.f / fmaxf(g_cnt[n], 1.f);
    uint4 a = g_xsumh[n * 2];
    uint4 b = g_xsumh[n * 2 + 1];
    unsigned int w[8] = {a.x, a.y, a.z, a.w, b.x, b.y, b.z, b.w};
    #pragma unroll
    for (int j = 0; j < 4; j++) {
        float2 lo = __half22float2(*(__half2*)&w[j * 2]);
        float2 hi = __half22float2(*(__half2*)&w[j * 2 + 1]);
        float4 rv = root1[n * 4 + j];
        float4 bv = bias1[j];
        float4 o;
        o.x = fmaxf(lo.x * inv + rv.x + bv.x, 0.f);
        o.y = fmaxf(lo.y * inv + rv.y + bv.y, 0.f);
        o.z = fmaxf(hi.x * inv + rv.z + bv.z, 0.f);
        o.w = fmaxf(hi.y * inv + rv.w + bv.w, 0.f);
        g_x[n * 4 + j] = o;
    }
}

// ---------------- K4: layer-2 edge pass: msg = x[src] @ w2[t], scatter-add ----------------
__global__ void k_edge2(const int* __restrict__ ei, const int* __restrict__ et) {
    __shared__ float4 sw2[RR * HH];  // 12.8 KB
    for (int i = threadIdx.x; i < RR * HH; i += blockDim.x) sw2[i] = g_w2[i];
    __syncthreads();

    int e = blockIdx.x * blockDim.x + threadIdx.x;
    if (e >= EE) return;
    int s = ei[e];
    int d = ei[EE + e];
    int t = et[e];

    const float4* xr = g_x + s * 4;
    float4 x0 = xr[0], x1 = xr[1], x2 = xr[2], x3 = xr[3];
    const float4* w = &sw2[t * HH];

    float4 acc = make_float4(0.f, 0.f, 0.f, 0.f);
    fma4(acc, x0.x, w[0]);  fma4(acc, x0.y, w[1]);  fma4(acc, x0.z, w[2]);  fma4(acc, x0.w, w[3]);
    fma4(acc, x1.x, w[4]);  fma4(acc, x1.y, w[5]);  fma4(acc, x1.z, w[6]);  fma4(acc, x1.w, w[7]);
    fma4(acc, x2.x, w[8]);  fma4(acc, x2.y, w[9]);  fma4(acc, x2.z, w[10]); fma4(acc, x2.w, w[11]);
    fma4(acc, x3.x, w[12]); fma4(acc, x3.y, w[13]); fma4(acc, x3.z, w[14]); fma4(acc, x3.w, w[15]);

    red4(&g_osum[d], acc);
}

// ---------------- K5: out = log_softmax(osum/max(cnt,1) + x @ root2 + bias2) ----------------
__global__ void k_out(const float4* __restrict__ root2, const float4* __restrict__ bias2,
                      float4* __restrict__ out) {
    __shared__ float4 sr2[HH];
    __shared__ float4 sb2;
    if (threadIdx.x < HH) sr2[threadIdx.x] = root2[threadIdx.x];
    if (threadIdx.x == 0) sb2 = bias2[0];
    __syncthreads();

    int n = blockIdx.x * blockDim.x + threadIdx.x;
    if (n >= NN) return;

    float inv = 1.f / fmaxf(g_cnt[n], 1.f);
    float4 os = g_osum[n];
    float4 acc;
    acc.x = os.x * inv + sb2.x;
    acc.y = os.y * inv + sb2.y;
    acc.z = os.z * inv + sb2.z;
    acc.w = os.w * inv + sb2.w;

    const float4* xr = g_x + n * 4;
    #pragma unroll
    for (int j = 0; j < 4; j++) {
        float4 xv = xr[j];
        fma4(acc, xv.x, sr2[j * 4 + 0]);
        fma4(acc, xv.y, sr2[j * 4 + 1]);
        fma4(acc, xv.z, sr2[j * 4 + 2]);
        fma4(acc, xv.w, sr2[j * 4 + 3]);
    }

    float m = fmaxf(fmaxf(acc.x, acc.y), fmaxf(acc.z, acc.w));
    float se = expf(acc.x - m) + expf(acc.y - m) + expf(acc.z - m) + expf(acc.w - m);
    float l = m + logf(se);
    float4 o;
    o.x = acc.x - l; o.y = acc.y - l; o.z = acc.z - l; o.w = acc.w - l;
    out[n] = o;
}

// ---------------- launcher ----------------
extern "C" void kernel_launch(void* const* d_in, const int* in_sizes, int n_in,
                              void* d_out, int out_size) {
    const int*    ei        = (const int*)d_in[0];         // edge_index [2,E] int32
    const int*    et        = (const int*)d_in[1];         // edge_type  [E]   int32
    // d_in[2] edge_norm: unused by the reference forward
    const float*  basis1    = (const float*)d_in[3];       // [B,N,H]
    const float*  comp1     = (const float*)d_in[4];       // [R,B]
    const float4* root1     = (const float4*)d_in[5];      // [N,H]
    const float4* bias1     = (const float4*)d_in[6];      // [H]
    const float*  basis2    = (const float*)d_in[7];       // [B,H,C]
    const float*  comp2     = (const float*)d_in[8];       // [R,B]
    const float4* root2     = (const float4*)d_in[9];      // [H,C]
    const float4* bias2     = (const float4*)d_in[10];     // [C]
    float4* out = (float4*)d_out;

    (void)in_sizes; (void)n_in; (void)out_size;

    k_zero <<<(NN * 2 + 255) / 256, 256>>>();
    k_w2   <<<1, 256>>>(comp2, basis2);
    k_w1   <<<(NH4 + 127) / 128, 128>>>((const float4*)basis1, comp1);
    k_edge1<<<(EE + 255) / 256, 256>>>(ei, et);
    k_x    <<<(NN + 255) / 256, 256>>>(root1, bias1);
    k_edge2<<<(EE + 255) / 256, 256>>>(ei, et);
    k_out  <<<(NN + 255) / 256, 256>>>(root2, bias2, out);
}